// round 5
// baseline (speedup 1.0000x reference)
#include <cuda_runtime.h>
#include <cuda_bf16.h>
#include <cstdint>
#include <math.h>

// ============================================================================
// Problem constants
// ============================================================================
#define HIDDEN   1024
#define BATCH    4096
#define M_TOTAL  16384          // BATCH * 4 pair rows
#define GCOLS    1024
#define NTOT     4096           // 4 interleaved weight matrices
#define KQ       3072
#define KZ       2048
#define BM       128
#define BN       128
#define BK       64             // bf16 elems per k-tile = 128 bytes/row
#define NKT      48             // KQ / BK
#define STAGES   4
#define STAGE_BYTES 32768       // A 16KB + B 16KB
#define OFF_BIAS (STAGES * STAGE_BYTES)     // 131072
#define OFF_RED  (OFF_BIAS + 512)
#define SMEM_USE (OFF_RED + 128)
#define SMEM_REQ (SMEM_USE + 1024)          // slack for manual 1KB align

// ============================================================================
// Scratch (__device__ globals; no allocation allowed)
// ============================================================================
__device__ __align__(128) __nv_bfloat16 g_cond[(size_t)M_TOTAL * KQ];  // 100 MB
__device__ __align__(128) __nv_bfloat16 g_Wt[(size_t)NTOT * KQ];       // 25 MB  [n=4g+j][k]
__device__ float g_bias[NTOT];
__device__ float g_kl_partial[4096];
__device__ float g_small4[4];

// ============================================================================
// PTX helpers (baseline sm_100 ISA only: cp.async, ldmatrix, mma.sync)
// ============================================================================
__device__ __forceinline__ uint32_t smem_to_u32(const void* p) {
    uint32_t a;
    asm("{ .reg .u64 t; cvta.to.shared.u64 t, %1; cvt.u32.u64 %0, t; }" : "=r"(a) : "l"(p));
    return a;
}
__device__ __forceinline__ void cp16(uint32_t dst, const void* src) {
    asm volatile("cp.async.cg.shared.global [%0], [%1], 16;" :: "r"(dst), "l"(src) : "memory");
}
#define CP_COMMIT() asm volatile("cp.async.commit_group;" ::: "memory")

#define LDSM4(r, addr) \
    asm volatile("ldmatrix.sync.aligned.m8n8.x4.shared.b16 {%0,%1,%2,%3}, [%4];" \
        : "=r"((r)[0]), "=r"((r)[1]), "=r"((r)[2]), "=r"((r)[3]) : "r"(addr))

#define MMA16816(c, a, b) \
    asm volatile("mma.sync.aligned.m16n8k16.row.col.f32.bf16.bf16.f32 " \
        "{%0,%1,%2,%3}, {%4,%5,%6,%7}, {%8,%9}, {%0,%1,%2,%3};" \
        : "+f"((c)[0]), "+f"((c)[1]), "+f"((c)[2]), "+f"((c)[3]) \
        : "r"((a)[0]), "r"((a)[1]), "r"((a)[2]), "r"((a)[3]), \
          "r"((b)[0]), "r"((b)[1]))

// ============================================================================
// Prep 1: cond[16384][3072] bf16 = [events[i,s] | events[i,s+1] | contexts[i,s]]
// ============================================================================
__global__ __launch_bounds__(256) void build_cond_kernel(
    const float* __restrict__ events, const float* __restrict__ contexts) {
    const int r = blockIdx.x;                 // 0..16383
    const int i = r >> 2, s = r & 3;
    const float* e0 = events + ((size_t)i * 5 + s) * HIDDEN;
    const float* e1 = e0 + HIDDEN;
    const float* cx = contexts + ((size_t)i * 4 + s) * HIDDEN;
    __nv_bfloat162* dst = (__nv_bfloat162*)(g_cond + (size_t)r * KQ);
    for (int t = threadIdx.x; t < 768; t += 256) {     // 768 float4 = 3072 floats
        const float* src = (t < 256) ? e0 : (t < 512) ? e1 : cx;
        float4 v = *(const float4*)(src + (size_t)(t & 255) * 4);
        dst[t * 2 + 0] = __floats2bfloat162_rn(v.x, v.y);
        dst[t * 2 + 1] = __floats2bfloat162_rn(v.z, v.w);
    }
}

// ============================================================================
// Prep 2: g_Wt[n=4g+j][k] = W_j[k][g]  (fp32 -> bf16, transposed+interleaved,
//          zero-padded for j<2, k>=2048)
// ============================================================================
__global__ void transpose_w_kernel(
    const float* __restrict__ Wz, const float* __restrict__ Wv,
    const float* __restrict__ Wqz, const float* __restrict__ Wqv) {
    __shared__ float tile[32][33];
    const int j = blockIdx.z;
    const float* W = (j == 0) ? Wz : (j == 1) ? Wv : (j == 2) ? Wqz : Wqv;
    const int Kd = (j < 2) ? KZ : KQ;
    const int k0 = blockIdx.x * 32, g0 = blockIdx.y * 32;
    const int tx = threadIdx.x, ty = threadIdx.y;
    const bool have = (k0 < Kd);
    if (have) {
        for (int i = ty; i < 32; i += 8)
            tile[i][tx] = W[(size_t)(k0 + i) * GCOLS + g0 + tx];
    }
    __syncthreads();
    for (int i = ty; i < 32; i += 8) {
        float v = have ? tile[tx][i] : 0.f;
        g_Wt[(size_t)(4 * (g0 + i) + j) * KQ + k0 + tx] = __float2bfloat16(v);
    }
}

// ============================================================================
// Prep 3: interleaved bias
// ============================================================================
__global__ void bias_kernel(
    const float* __restrict__ bz, const float* __restrict__ bv,
    const float* __restrict__ bqz, const float* __restrict__ bqv) {
    const int i = blockIdx.x * 256 + threadIdx.x;    // < 4096
    const int g = i >> 2, j = i & 3;
    const float* b = (j == 0) ? bz : (j == 1) ? bv : (j == 2) ? bqz : bqv;
    g_bias[i] = b[g];
}

// ============================================================================
// Small losses: cross-entropy + logic sums (one block, deterministic)
// ============================================================================
__global__ __launch_bounds__(1024) void small_loss_kernel(
    const float* __restrict__ ps, const float* __restrict__ pt,
    const float* __restrict__ pc, const int* __restrict__ labels,
    const int* __restrict__ scene, const int* __restrict__ thr) {
    __shared__ float red[1024];
    float wce = 0.f, wsum = 0.f, tsum = 0.f, vsum = 0.f;
    for (int b = threadIdx.x; b < BATCH; b += 1024) {
        const int lab = labels[b];
        const int s = scene[b], t = thr[b];
        const bool l5 = (lab == 5), l2 = (lab == 2), l3 = (lab == 3);
        const bool le = !(l5 | l2 | l3);
        const int nv = l5 ? 3 : (l2 ? 1 : (l3 ? 2 : 3));
        const int last = nv - 1;
        const float* psb = ps + (size_t)b * 6;
        const float* ptb = pt + (size_t)b * 6;
        const float* pcb = pc + (size_t)b * 6;
        #pragma unroll
        for (int slot = 0; slot < 3; slot++) {
            if (slot >= nv) break;
            int chain = l5 ? 1 : (l2 ? 0 : (l3 ? (slot == 0 ? 1 : 0)
                                               : (slot == 2 ? 0 : 1)));
            int ps_col = (!l5 && slot == last) ? s : 0;
            int pt_row = (l3 && slot == 1) ? (t == 1 ? 0 : 1) : slot;
            int pt_col = (l2 && slot == 0) ? t : ((le && slot == 2) ? t : 0);
            int pcs_col = l5 ? 1 : (slot == last ? 0 : 1);
            float PS = psb[slot * 2 + ps_col];
            float PT = ptb[pt_row * 2 + pt_col];
            float PCS = pcb[slot * 2 + pcs_col];
            float a0 = pcb[slot * 2 + 0], a1 = pcb[slot * 2 + 1];
            float mx = fmaxf(a0, a1);
            float lse = mx + logf(expf(a0 - mx) + expf(a1 - mx));
            float logp = (chain == 0 ? a0 : a1) - lse;
            float w = (chain == 0) ? 0.6f : 0.4f;
            wce += -w * logp;
            wsum += w;
            float lsig = fminf(PCS, 0.f) - log1pf(expf(-fabsf(PCS)));
            tsum += fabsf(logf(PS) + logf(PT) - lsig);
            vsum += 1.f;
        }
    }
    const int tid = threadIdx.x;
    float vals[4] = {wce, wsum, tsum, vsum};
    for (int v = 0; v < 4; v++) {
        red[tid] = vals[v];
        __syncthreads();
        for (int sft = 512; sft > 0; sft >>= 1) {
            if (tid < sft) red[tid] += red[tid + sft];
            __syncthreads();
        }
        if (tid == 0) g_small4[v] = red[0];
        __syncthreads();
    }
}

// ============================================================================
// Fused GEMM + KL epilogue (mma.sync bf16).
// C[16384, 4096] = cond[16384,3072] @ g_Wt^T, columns interleaved 4g+j.
// grid (32 n-tiles, 128 m-tiles), 256 threads = 8 warps (4M x 2N).
// ============================================================================
__global__ __launch_bounds__(256, 1) void gemm_kl_kernel() {
    extern __shared__ char dsm[];
    const uint32_t raw = smem_to_u32(dsm);
    const uint32_t sb = (raw + 1023u) & ~1023u;
    char* smc = dsm + (sb - raw);
    const int tid = threadIdx.x;
    const int lane = tid & 31;
    const int wid = tid >> 5;
    const int n0 = blockIdx.x * BN;
    const int m0 = blockIdx.y * BM;

    float* sBias = (float*)(smc + OFF_BIAS);
    if (tid < 128) sBias[tid] = g_bias[n0 + tid];

    // ---- per-lane ldmatrix address components (xor swizzle) ----
    const int wm = wid & 3;          // 4 warps along M
    const int wn = wid >> 2;         // 2 warps along N
    const int ar0 = wm * 32 + (lane & 15);
    const int ar1 = ar0 + 16;
    const uint32_t aoff0 = (uint32_t)ar0 * 128u, aswz0 = (uint32_t)(ar0 & 7) * 16u;
    const uint32_t aoff1 = (uint32_t)ar1 * 128u, aswz1 = (uint32_t)(ar1 & 7) * 16u;
    const uint32_t acb = (uint32_t)(lane >> 4) * 16u;
    uint32_t boff[4], bswz[4];
    {
        const int brbase = wn * 64 + ((lane >> 4) << 3) + (lane & 7);
#pragma unroll
        for (int p = 0; p < 4; p++) {
            const int br = brbase + p * 16;
            boff[p] = (uint32_t)br * 128u;
            bswz[p] = (uint32_t)(br & 7) * 16u;
        }
    }
    const uint32_t bcb = (uint32_t)((lane >> 3) & 1) * 16u;

    float acc[2][8][4];
#pragma unroll
    for (int i = 0; i < 2; i++)
#pragma unroll
        for (int j = 0; j < 8; j++)
#pragma unroll
            for (int c = 0; c < 4; c++) acc[i][j][c] = 0.f;

    // ---- async tile loader: 2048 x 16B chunks per stage, 8 per thread ----
    auto load_stage = [&](int kt, int st) {
        const uint32_t stA = sb + (uint32_t)st * STAGE_BYTES;
        const uint32_t stB = stA + 16384u;
        const int kbyte = kt * (BK * 2);
#pragma unroll
        for (int it = 0; it < 8; it++) {
            const int c = tid + it * 256;
            const int row = (c & 1023) >> 3;
            const int cb = c & 7;
            const uint32_t off = (uint32_t)row * 128u +
                (((uint32_t)cb * 16u) ^ ((uint32_t)(row & 7) * 16u));
            if (c < 1024) {
                const char* src = (const char*)(g_cond + (size_t)(m0 + row) * KQ) + kbyte + cb * 16;
                cp16(stA + off, src);
            } else {
                const char* src = (const char*)(g_Wt + (size_t)(n0 + row) * KQ) + kbyte + cb * 16;
                cp16(stB + off, src);
            }
        }
        CP_COMMIT();
    };

    load_stage(0, 0);
    load_stage(1, 1);
    load_stage(2, 2);

    for (int kt = 0; kt < NKT; kt++) {
        if (kt < NKT - 2)       { asm volatile("cp.async.wait_group 2;" ::: "memory"); }
        else if (kt == NKT - 2) { asm volatile("cp.async.wait_group 1;" ::: "memory"); }
        else                    { asm volatile("cp.async.wait_group 0;" ::: "memory"); }
        __syncthreads();
        if (kt + STAGES - 1 < NKT) load_stage(kt + 3, (kt + 3) & 3);

        const uint32_t stA = sb + (uint32_t)(kt & 3) * STAGE_BYTES;
        const uint32_t stB = stA + 16384u;
#pragma unroll
        for (int ks = 0; ks < 4; ks++) {
            const uint32_t kb = (uint32_t)ks * 32u;
            uint32_t a0[4], a1[4];
            LDSM4(a0, stA + aoff0 + ((kb + acb) ^ aswz0));
            LDSM4(a1, stA + aoff1 + ((kb + acb) ^ aswz1));
            uint32_t bfr[8][2];
#pragma unroll
            for (int p = 0; p < 4; p++) {
                uint32_t r[4];
                LDSM4(r, stB + boff[p] + ((kb + bcb) ^ bswz[p]));
                bfr[2 * p][0] = r[0]; bfr[2 * p][1] = r[1];
                bfr[2 * p + 1][0] = r[2]; bfr[2 * p + 1][1] = r[3];
            }
#pragma unroll
            for (int ni = 0; ni < 8; ni++) {
                MMA16816(acc[0][ni], a0, bfr[ni]);
                MMA16816(acc[1][ni], a1, bfr[ni]);
            }
        }
    }

    // ---- fused KL epilogue ----
    // col = wn*64 + ni*8 + (lane%4)*2 + {0,1}; even lanes hold (z_mean,z_lv),
    // odd neighbor (lane^1) holds (q_mean,q_lv) of the same g.
    float acckl = 0.f;
#pragma unroll
    for (int mi = 0; mi < 2; mi++) {
#pragma unroll
        for (int ni = 0; ni < 8; ni++) {
            const int cb = wn * 64 + ni * 8 + (lane & 3) * 2;
            const float b0v = sBias[cb], b1v = sBias[cb + 1];
#pragma unroll
            for (int r = 0; r < 2; r++) {
                float v0 = acc[mi][ni][2 * r]     + b0v;
                float v1 = acc[mi][ni][2 * r + 1] + b1v;
                float o0 = __shfl_xor_sync(0xFFFFFFFFu, v0, 1);
                float o1 = __shfl_xor_sync(0xFFFFFFFFu, v1, 1);
                if ((lane & 1) == 0) {
                    // v0=z_mean, v1=z_lv, o0=q_mean, o1=q_lv
                    float d = v0 - o0;
                    acckl += o1 - v1 + (expf(v1) + d * d) * expf(-o1) - 1.f;
                }
            }
        }
    }

    // deterministic reduction
#pragma unroll
    for (int s = 16; s > 0; s >>= 1)
        acckl += __shfl_down_sync(0xFFFFFFFFu, acckl, s);
    float* red = (float*)(smc + OFF_RED);
    if (lane == 0) red[wid] = acckl;
    __syncthreads();
    if (tid == 0) {
        float s = 0.f;
        for (int w = 0; w < 8; w++) s += red[w];
        g_kl_partial[blockIdx.y * 32 + blockIdx.x] = s;
    }
}

// ============================================================================
// Final combine
// ============================================================================
__global__ __launch_bounds__(1024) void combine_kernel(float* __restrict__ out) {
    __shared__ float red[1024];
    float s = 0.f;
    for (int i = threadIdx.x; i < 4096; i += 1024) s += g_kl_partial[i];
    red[threadIdx.x] = s;
    __syncthreads();
    for (int sft = 512; sft > 0; sft >>= 1) {
        if (threadIdx.x < sft) red[threadIdx.x] += red[threadIdx.x + sft];
        __syncthreads();
    }
    if (threadIdx.x == 0) {
        const float kl_loss = 0.5f * red[0] / (float)M_TOTAL;
        out[0] = g_small4[0] / g_small4[1] + kl_loss + g_small4[2] / g_small4[3];
    }
}

// ============================================================================
// kernel_launch
// ============================================================================
extern "C" void kernel_launch(void* const* d_in, const int* in_sizes, int n_in,
                              void* d_out, int out_size) {
    const float* events   = (const float*)d_in[0];
    const float* contexts = (const float*)d_in[1];
    const float* ps       = (const float*)d_in[2];
    const float* pt       = (const float*)d_in[3];
    const float* pc       = (const float*)d_in[4];
    const int*   labels   = (const int*)d_in[5];
    const int*   scene    = (const int*)d_in[6];
    const int*   thr      = (const int*)d_in[7];
    const float* Wz  = (const float*)d_in[8];
    const float* bz  = (const float*)d_in[9];
    const float* Wv  = (const float*)d_in[10];
    const float* bv  = (const float*)d_in[11];
    const float* Wqz = (const float*)d_in[12];
    const float* bqz = (const float*)d_in[13];
    const float* Wqv = (const float*)d_in[14];
    const float* bqv = (const float*)d_in[15];
    float* out = (float*)d_out;

    cudaFuncSetAttribute(gemm_kl_kernel,
                         cudaFuncAttributeMaxDynamicSharedMemorySize, SMEM_REQ);

    build_cond_kernel<<<M_TOTAL, 256>>>(events, contexts);
    transpose_w_kernel<<<dim3(KQ / 32, GCOLS / 32, 4), dim3(32, 8)>>>(Wz, Wv, Wqz, Wqv);
    bias_kernel<<<NTOT / 256, 256>>>(bz, bv, bqz, bqv);
    small_loss_kernel<<<1, 1024>>>(ps, pt, pc, labels, scene, thr);
    gemm_kl_kernel<<<dim3(NTOT / BN, M_TOTAL / BM), 256, SMEM_REQ>>>();
    combine_kernel<<<1, 1024>>>(out);
}

// round 6
// speedup vs baseline: 1.0750x; 1.0750x over previous
#include <cuda_runtime.h>
#include <cuda_bf16.h>
#include <cstdint>
#include <math.h>

// ============================================================================
// Problem constants
// ============================================================================
#define HIDDEN   1024
#define BATCH    4096
#define M_TOTAL  16384          // BATCH * 4 pair rows
#define GCOLS    1024
#define KQ       3072
#define KZ       2048
#define BM       128
#define BK       64             // bf16 elems per k-tile = 128 bytes/row
#define NKT      48             // KQ / BK
#define NKT_Z    32             // KZ / BK
#define STAGES   4
#define STAGE_BYTES 49152       // A 16KB + Bz 16KB + Bq 16KB
#define OFF_BIAS (STAGES * STAGE_BYTES)     // 196608
#define OFF_RED  (OFF_BIAS + 1024)
#define SMEM_USE (OFF_RED + 128)
#define SMEM_REQ (SMEM_USE + 1024)          // slack for manual 1KB align

// ============================================================================
// Scratch (__device__ globals; no allocation allowed)
// ============================================================================
__device__ __align__(128) __nv_bfloat16 g_cond[(size_t)M_TOTAL * KQ]; // 100 MB
__device__ __align__(128) __nv_bfloat16 g_Wz2[(size_t)2048 * KZ];     // 8 MB  [(2g+j)][k]
__device__ __align__(128) __nv_bfloat16 g_Wq2[(size_t)2048 * KQ];     // 12 MB [(2g+j)][k]
__device__ float g_bias_z2[2048];
__device__ float g_bias_q2[2048];
__device__ float g_kl_partial[2048];
__device__ float g_small4[4];

// ============================================================================
// PTX helpers (baseline sm_100 ISA only: cp.async, ldmatrix, mma.sync)
// ============================================================================
__device__ __forceinline__ uint32_t smem_to_u32(const void* p) {
    uint32_t a;
    asm("{ .reg .u64 t; cvta.to.shared.u64 t, %1; cvt.u32.u64 %0, t; }" : "=r"(a) : "l"(p));
    return a;
}
__device__ __forceinline__ void cp16(uint32_t dst, const void* src) {
    asm volatile("cp.async.cg.shared.global [%0], [%1], 16;" :: "r"(dst), "l"(src) : "memory");
}
#define CP_COMMIT() asm volatile("cp.async.commit_group;" ::: "memory")

#define LDSM4(r, addr) \
    asm volatile("ldmatrix.sync.aligned.m8n8.x4.shared.b16 {%0,%1,%2,%3}, [%4];" \
        : "=r"((r)[0]), "=r"((r)[1]), "=r"((r)[2]), "=r"((r)[3]) : "r"(addr))

#define MMA16816(c, a, b0, b1) \
    asm volatile("mma.sync.aligned.m16n8k16.row.col.f32.bf16.bf16.f32 " \
        "{%0,%1,%2,%3}, {%4,%5,%6,%7}, {%8,%9}, {%0,%1,%2,%3};" \
        : "+f"((c)[0]), "+f"((c)[1]), "+f"((c)[2]), "+f"((c)[3]) \
        : "r"((a)[0]), "r"((a)[1]), "r"((a)[2]), "r"((a)[3]), \
          "r"(b0), "r"(b1))

// ============================================================================
// Prep 1: cond[16384][3072] bf16 = [events[i,s] | events[i,s+1] | contexts[i,s]]
// ============================================================================
__global__ __launch_bounds__(256) void build_cond_kernel(
    const float* __restrict__ events, const float* __restrict__ contexts) {
    const int r = blockIdx.x;                 // 0..16383
    const int i = r >> 2, s = r & 3;
    const float* e0 = events + ((size_t)i * 5 + s) * HIDDEN;
    const float* e1 = e0 + HIDDEN;
    const float* cx = contexts + ((size_t)i * 4 + s) * HIDDEN;
    __nv_bfloat162* dst = (__nv_bfloat162*)(g_cond + (size_t)r * KQ);
    for (int t = threadIdx.x; t < 768; t += 256) {     // 768 float4 = 3072 floats
        const float* src = (t < 256) ? e0 : (t < 512) ? e1 : cx;
        float4 v = *(const float4*)(src + (size_t)(t & 255) * 4);
        dst[t * 2 + 0] = __floats2bfloat162_rn(v.x, v.y);
        dst[t * 2 + 1] = __floats2bfloat162_rn(v.z, v.w);
    }
}

// ============================================================================
// Prep 2: pair-interleaved transposed weights (no zero padding)
//   g_Wz2[(2g+j)][k] = (j? Wv : Wz)[k][g],  k < 2048
//   g_Wq2[(2g+j)][k] = (j? Wqv: Wqz)[k][g], k < 3072
// ============================================================================
__global__ void transpose_w_kernel(
    const float* __restrict__ Wz, const float* __restrict__ Wv,
    const float* __restrict__ Wqz, const float* __restrict__ Wqv) {
    __shared__ float tile[32][33];
    const int j = blockIdx.z;
    const float* W = (j == 0) ? Wz : (j == 1) ? Wv : (j == 2) ? Wqz : Wqv;
    const int Kd = (j < 2) ? KZ : KQ;
    const int k0 = blockIdx.x * 32, g0 = blockIdx.y * 32;
    if (k0 >= Kd) return;
    const int tx = threadIdx.x, ty = threadIdx.y;
    for (int i = ty; i < 32; i += 8)
        tile[i][tx] = W[(size_t)(k0 + i) * GCOLS + g0 + tx];
    __syncthreads();
    for (int i = ty; i < 32; i += 8) {
        const float v = tile[tx][i];
        if (j < 2)
            g_Wz2[(size_t)(2 * (g0 + i) + j) * KZ + k0 + tx] = __float2bfloat16(v);
        else
            g_Wq2[(size_t)(2 * (g0 + i) + (j - 2)) * KQ + k0 + tx] = __float2bfloat16(v);
    }
}

// ============================================================================
// Prep 3: pair-interleaved biases
// ============================================================================
__global__ void bias_kernel(
    const float* __restrict__ bz, const float* __restrict__ bv,
    const float* __restrict__ bqz, const float* __restrict__ bqv) {
    const int i = blockIdx.x * 256 + threadIdx.x;    // < 2048
    const int g = i >> 1, j = i & 1;
    g_bias_z2[i] = (j == 0) ? bz[g] : bv[g];
    g_bias_q2[i] = (j == 0) ? bqz[g] : bqv[g];
}

// ============================================================================
// Small losses: cross-entropy + logic sums (one block, deterministic)
// ============================================================================
__global__ __launch_bounds__(1024) void small_loss_kernel(
    const float* __restrict__ ps, const float* __restrict__ pt,
    const float* __restrict__ pc, const int* __restrict__ labels,
    const int* __restrict__ scene, const int* __restrict__ thr) {
    __shared__ float red[1024];
    float wce = 0.f, wsum = 0.f, tsum = 0.f, vsum = 0.f;
    for (int b = threadIdx.x; b < BATCH; b += 1024) {
        const int lab = labels[b];
        const int s = scene[b], t = thr[b];
        const bool l5 = (lab == 5), l2 = (lab == 2), l3 = (lab == 3);
        const bool le = !(l5 | l2 | l3);
        const int nv = l5 ? 3 : (l2 ? 1 : (l3 ? 2 : 3));
        const int last = nv - 1;
        const float* psb = ps + (size_t)b * 6;
        const float* ptb = pt + (size_t)b * 6;
        const float* pcb = pc + (size_t)b * 6;
        #pragma unroll
        for (int slot = 0; slot < 3; slot++) {
            if (slot >= nv) break;
            int chain = l5 ? 1 : (l2 ? 0 : (l3 ? (slot == 0 ? 1 : 0)
                                               : (slot == 2 ? 0 : 1)));
            int ps_col = (!l5 && slot == last) ? s : 0;
            int pt_row = (l3 && slot == 1) ? (t == 1 ? 0 : 1) : slot;
            int pt_col = (l2 && slot == 0) ? t : ((le && slot == 2) ? t : 0);
            int pcs_col = l5 ? 1 : (slot == last ? 0 : 1);
            float PS = psb[slot * 2 + ps_col];
            float PT = ptb[pt_row * 2 + pt_col];
            float PCS = pcb[slot * 2 + pcs_col];
            float a0 = pcb[slot * 2 + 0], a1 = pcb[slot * 2 + 1];
            float mx = fmaxf(a0, a1);
            float lse = mx + logf(expf(a0 - mx) + expf(a1 - mx));
            float logp = (chain == 0 ? a0 : a1) - lse;
            float w = (chain == 0) ? 0.6f : 0.4f;
            wce += -w * logp;
            wsum += w;
            float lsig = fminf(PCS, 0.f) - log1pf(expf(-fabsf(PCS)));
            tsum += fabsf(logf(PS) + logf(PT) - lsig);
            vsum += 1.f;
        }
    }
    const int tid = threadIdx.x;
    float vals[4] = {wce, wsum, tsum, vsum};
    for (int v = 0; v < 4; v++) {
        red[tid] = vals[v];
        __syncthreads();
        for (int sft = 512; sft > 0; sft >>= 1) {
            if (tid < sft) red[tid] += red[tid + sft];
            __syncthreads();
        }
        if (tid == 0) g_small4[v] = red[0];
        __syncthreads();
    }
}

// ============================================================================
// No-op kernel: shifts gemm_kl_kernel to ncu capture slot (-s 5 -c 1)
// ============================================================================
__global__ void dummy_kernel() {}

// ============================================================================
// Fused dual-GEMM + KL epilogue (mma.sync bf16).
//   Cz[16384,2048] = cond[:, :2048] @ g_Wz2^T      (pair-interleaved zm/zlv)
//   Cq[16384,2048] = cond            @ g_Wq2^T     (pair-interleaved qm/qlv)
// grid (16 g-blocks, 128 m-tiles), 512 threads = 16 warps (4M x 4N).
// Each CTA: rows [m0,m0+128), z cols + q cols [nb0, nb0+128).
// ============================================================================
__global__ __launch_bounds__(512, 1) void gemm_kl_kernel() {
    extern __shared__ char dsm[];
    const uint32_t raw = smem_to_u32(dsm);
    const uint32_t sb = (raw + 1023u) & ~1023u;
    char* smc = dsm + (sb - raw);
    const int tid = threadIdx.x;
    const int lane = tid & 31;
    const int wid = tid >> 5;
    const int nb0 = blockIdx.x * 128;     // interleaved col base (64 groups)
    const int m0 = blockIdx.y * BM;

    float* sBiasZ = (float*)(smc + OFF_BIAS);
    float* sBiasQ = sBiasZ + 128;
    if (tid < 128) {
        sBiasZ[tid] = g_bias_z2[nb0 + tid];
        sBiasQ[tid] = g_bias_q2[nb0 + tid];
    }

    // ---- per-lane ldmatrix address components (xor swizzle) ----
    const int wm = wid & 3;          // 4 warps along M
    const int wn = wid >> 2;         // 4 warps along N (32 cols each of z and q)
    const int ar0 = wm * 32 + (lane & 15);
    const int ar1 = ar0 + 16;
    const uint32_t aoff0 = (uint32_t)ar0 * 128u, aswz0 = (uint32_t)(ar0 & 7) * 16u;
    const uint32_t aoff1 = (uint32_t)ar1 * 128u, aswz1 = (uint32_t)(ar1 & 7) * 16u;
    const uint32_t acb = (uint32_t)(lane >> 4) * 16u;
    // B rows (shared pattern for z and q tiles)
    uint32_t boff[2], bswz[2];
    {
        const int brbase = wn * 32 + ((lane >> 4) << 3) + (lane & 7);
#pragma unroll
        for (int p = 0; p < 2; p++) {
            const int br = brbase + p * 16;
            boff[p] = (uint32_t)br * 128u;
            bswz[p] = (uint32_t)(br & 7) * 16u;
        }
    }
    const uint32_t bcb = (uint32_t)((lane >> 3) & 1) * 16u;

    float accZ[2][4][4], accQ[2][4][4];
#pragma unroll
    for (int i = 0; i < 2; i++)
#pragma unroll
        for (int j = 0; j < 4; j++)
#pragma unroll
            for (int c = 0; c < 4; c++) { accZ[i][j][c] = 0.f; accQ[i][j][c] = 0.f; }

    // ---- async tile loader ----
    // stage layout: [A 16KB][Bz 16KB][Bq 16KB]; Bz skipped for kt >= 32
    auto load_stage = [&](int kt, int st) {
        const uint32_t base = sb + (uint32_t)st * STAGE_BYTES;
        const int kbyte = kt * 128;
        const bool full = (kt < NKT_Z);
        const int nch = full ? 3072 : 2048;
        for (int c = tid; c < nch; c += 512) {
            const int sec = c >> 10;
            const int row = (c & 1023) >> 3;
            const int cb = c & 7;
            const uint32_t off = (uint32_t)row * 128u +
                (((uint32_t)cb * 16u) ^ ((uint32_t)(row & 7) * 16u));
            if (sec == 0) {
                const char* src = (const char*)(g_cond + (size_t)(m0 + row) * KQ) + kbyte + cb * 16;
                cp16(base + off, src);
            } else if (full && sec == 1) {
                const char* src = (const char*)(g_Wz2 + (size_t)(nb0 + row) * KZ) + kbyte + cb * 16;
                cp16(base + 16384u + off, src);
            } else {
                const char* src = (const char*)(g_Wq2 + (size_t)(nb0 + row) * KQ) + kbyte + cb * 16;
                cp16(base + 32768u + off, src);
            }
        }
        CP_COMMIT();
    };

    load_stage(0, 0);
    load_stage(1, 1);
    load_stage(2, 2);

    for (int kt = 0; kt < NKT; kt++) {
        if (kt < NKT - 2)       { asm volatile("cp.async.wait_group 2;" ::: "memory"); }
        else if (kt == NKT - 2) { asm volatile("cp.async.wait_group 1;" ::: "memory"); }
        else                    { asm volatile("cp.async.wait_group 0;" ::: "memory"); }
        __syncthreads();
        if (kt + 3 < NKT) load_stage(kt + 3, (kt + 3) & 3);

        const uint32_t stA = sb + (uint32_t)(kt & 3) * STAGE_BYTES;
        const uint32_t stBz = stA + 16384u;
        const uint32_t stBq = stA + 32768u;
        const bool full = (kt < NKT_Z);
#pragma unroll
        for (int ks = 0; ks < 4; ks++) {
            const uint32_t kb = (uint32_t)ks * 32u;
            uint32_t a0[4], a1[4];
            LDSM4(a0, stA + aoff0 + ((kb + acb) ^ aswz0));
            LDSM4(a1, stA + aoff1 + ((kb + acb) ^ aswz1));
            uint32_t qf[2][4];
            LDSM4(qf[0], stBq + boff[0] + ((kb + bcb) ^ bswz[0]));
            LDSM4(qf[1], stBq + boff[1] + ((kb + bcb) ^ bswz[1]));
#pragma unroll
            for (int p = 0; p < 2; p++) {
#pragma unroll
                for (int h = 0; h < 2; h++) {
                    MMA16816(accQ[0][p * 2 + h], a0, qf[p][2 * h], qf[p][2 * h + 1]);
                    MMA16816(accQ[1][p * 2 + h], a1, qf[p][2 * h], qf[p][2 * h + 1]);
                }
            }
            if (full) {
                uint32_t zf[2][4];
                LDSM4(zf[0], stBz + boff[0] + ((kb + bcb) ^ bswz[0]));
                LDSM4(zf[1], stBz + boff[1] + ((kb + bcb) ^ bswz[1]));
#pragma unroll
                for (int p = 0; p < 2; p++) {
#pragma unroll
                    for (int h = 0; h < 2; h++) {
                        MMA16816(accZ[0][p * 2 + h], a0, zf[p][2 * h], zf[p][2 * h + 1]);
                        MMA16816(accZ[1][p * 2 + h], a1, zf[p][2 * h], zf[p][2 * h + 1]);
                    }
                }
            }
        }
    }

    // ---- fused KL epilogue (no shuffles: each lane owns full (zm,zlv,qm,qlv)) ----
    // col (interleaved) = wn*32 + ni*8 + (lane&3)*2 + {0,1}
    float acckl = 0.f;
#pragma unroll
    for (int mi = 0; mi < 2; mi++) {
#pragma unroll
        for (int ni = 0; ni < 4; ni++) {
            const int col = wn * 32 + ni * 8 + (lane & 3) * 2;
            const float bzm = sBiasZ[col], bzl = sBiasZ[col + 1];
            const float bqm = sBiasQ[col], bql = sBiasQ[col + 1];
#pragma unroll
            for (int h = 0; h < 2; h++) {
                const float zm = accZ[mi][ni][2 * h]     + bzm;
                const float zl = accZ[mi][ni][2 * h + 1] + bzl;
                const float qm = accQ[mi][ni][2 * h]     + bqm;
                const float ql = accQ[mi][ni][2 * h + 1] + bql;
                const float d = zm - qm;
                acckl += ql - zl + (expf(zl) + d * d) * expf(-ql) - 1.f;
            }
        }
    }

    // deterministic reduction over 16 warps
#pragma unroll
    for (int s = 16; s > 0; s >>= 1)
        acckl += __shfl_down_sync(0xFFFFFFFFu, acckl, s);
    float* red = (float*)(smc + OFF_RED);
    if (lane == 0) red[wid] = acckl;
    __syncthreads();
    if (tid == 0) {
        float s = 0.f;
        for (int w = 0; w < 16; w++) s += red[w];
        g_kl_partial[blockIdx.y * 16 + blockIdx.x] = s;
    }
}

// ============================================================================
// Final combine
// ============================================================================
__global__ __launch_bounds__(1024) void combine_kernel(float* __restrict__ out) {
    __shared__ float red[1024];
    float s = 0.f;
    for (int i = threadIdx.x; i < 2048; i += 1024) s += g_kl_partial[i];
    red[threadIdx.x] = s;
    __syncthreads();
    for (int sft = 512; sft > 0; sft >>= 1) {
        if (threadIdx.x < sft) red[threadIdx.x] += red[threadIdx.x + sft];
        __syncthreads();
    }
    if (threadIdx.x == 0) {
        const float kl_loss = 0.5f * red[0] / (float)M_TOTAL;
        out[0] = g_small4[0] / g_small4[1] + kl_loss + g_small4[2] / g_small4[3];
    }
}

// ============================================================================
// kernel_launch
// ============================================================================
extern "C" void kernel_launch(void* const* d_in, const int* in_sizes, int n_in,
                              void* d_out, int out_size) {
    const float* events   = (const float*)d_in[0];
    const float* contexts = (const float*)d_in[1];
    const float* ps       = (const float*)d_in[2];
    const float* pt       = (const float*)d_in[3];
    const float* pc       = (const float*)d_in[4];
    const int*   labels   = (const int*)d_in[5];
    const int*   scene    = (const int*)d_in[6];
    const int*   thr      = (const int*)d_in[7];
    const float* Wz  = (const float*)d_in[8];
    const float* bz  = (const float*)d_in[9];
    const float* Wv  = (const float*)d_in[10];
    const float* bv  = (const float*)d_in[11];
    const float* Wqz = (const float*)d_in[12];
    const float* bqz = (const float*)d_in[13];
    const float* Wqv = (const float*)d_in[14];
    const float* bqv = (const float*)d_in[15];
    float* out = (float*)d_out;

    cudaFuncSetAttribute(gemm_kl_kernel,
                         cudaFuncAttributeMaxDynamicSharedMemorySize, SMEM_REQ);

    build_cond_kernel<<<M_TOTAL, 256>>>(events, contexts);                       // launch 0
    transpose_w_kernel<<<dim3(KQ / 32, GCOLS / 32, 4), dim3(32, 8)>>>(Wz, Wv, Wqz, Wqv); // 1
    bias_kernel<<<2048 / 256, 256>>>(bz, bv, bqz, bqv);                          // 2
    small_loss_kernel<<<1, 1024>>>(ps, pt, pc, labels, scene, thr);              // 3
    dummy_kernel<<<1, 32>>>();                                                   // 4
    gemm_kl_kernel<<<dim3(16, M_TOTAL / BM), 512, SMEM_REQ>>>();                 // 5  <- ncu -s 5
    combine_kernel<<<1, 1024>>>(out);                                            // 6
}

// round 7
// speedup vs baseline: 1.1074x; 1.0301x over previous
#include <cuda_runtime.h>
#include <cuda_bf16.h>
#include <cstdint>
#include <math.h>

// ============================================================================
// Problem constants
// ============================================================================
#define HIDDEN   1024
#define BATCH    4096
#define M_TOTAL  16384          // BATCH * 4 pair rows
#define GCOLS    1024
#define KQ       3072
#define KZ       2048
#define BM       128
#define BG       64             // g-columns per CTA
#define NKT      48             // KQ / 64
#define NKT_Z    32             // KZ / 64
#define STAGE_BYTES 40960       // A 16KB + Bd 8KB + Bql 8KB + Bzl 8KB
#define OFF_BIAS (4 * STAGE_BYTES)          // 163840
#define OFF_RED  (OFF_BIAS + 768)
#define SMEM_USE (OFF_RED + 128)
#define SMEM_REQ (SMEM_USE + 1024)          // slack for manual 1KB align

// ============================================================================
// Scratch (__device__ globals; no allocation allowed)
// ============================================================================
__device__ __align__(128) __nv_bfloat16 g_cond[(size_t)M_TOTAL * KQ]; // 100 MB
__device__ __align__(128) __nv_bfloat16 g_Wd [(size_t)GCOLS * KQ];    // 6 MB  [g][k]
__device__ __align__(128) __nv_bfloat16 g_Wzl[(size_t)GCOLS * KZ];    // 4 MB
__device__ __align__(128) __nv_bfloat16 g_Wql[(size_t)GCOLS * KQ];    // 6 MB
__device__ float g_kl_partial[2048];
__device__ float g_small4[4];

// ============================================================================
// PTX helpers (baseline sm_100 ISA only: cp.async, ldmatrix, mma.sync)
// ============================================================================
__device__ __forceinline__ uint32_t smem_to_u32(const void* p) {
    uint32_t a;
    asm("{ .reg .u64 t; cvta.to.shared.u64 t, %1; cvt.u32.u64 %0, t; }" : "=r"(a) : "l"(p));
    return a;
}
__device__ __forceinline__ void cp16(uint32_t dst, const void* src) {
    asm volatile("cp.async.cg.shared.global [%0], [%1], 16;" :: "r"(dst), "l"(src) : "memory");
}
#define CP_COMMIT() asm volatile("cp.async.commit_group;" ::: "memory")

#define LDSM4(r, addr) \
    asm volatile("ldmatrix.sync.aligned.m8n8.x4.shared.b16 {%0,%1,%2,%3}, [%4];" \
        : "=r"((r)[0]), "=r"((r)[1]), "=r"((r)[2]), "=r"((r)[3]) : "r"(addr))

#define MMA16816(c, a, b0, b1) \
    asm volatile("mma.sync.aligned.m16n8k16.row.col.f32.bf16.bf16.f32 " \
        "{%0,%1,%2,%3}, {%4,%5,%6,%7}, {%8,%9}, {%0,%1,%2,%3};" \
        : "+f"((c)[0]), "+f"((c)[1]), "+f"((c)[2]), "+f"((c)[3]) \
        : "r"((a)[0]), "r"((a)[1]), "r"((a)[2]), "r"((a)[3]), \
          "r"(b0), "r"(b1))

// ============================================================================
// Prep 1: cond[16384][3072] bf16 = [events[i,s] | events[i,s+1] | contexts[i,s]]
// ============================================================================
__global__ __launch_bounds__(256) void build_cond_kernel(
    const float* __restrict__ events, const float* __restrict__ contexts) {
    const int r = blockIdx.x;                 // 0..16383
    const int i = r >> 2, s = r & 3;
    const float* e0 = events + ((size_t)i * 5 + s) * HIDDEN;
    const float* e1 = e0 + HIDDEN;
    const float* cx = contexts + ((size_t)i * 4 + s) * HIDDEN;
    __nv_bfloat162* dst = (__nv_bfloat162*)(g_cond + (size_t)r * KQ);
    for (int t = threadIdx.x; t < 768; t += 256) {     // 768 float4 = 3072 floats
        const float* src = (t < 256) ? e0 : (t < 512) ? e1 : cx;
        float4 v = *(const float4*)(src + (size_t)(t & 255) * 4);
        dst[t * 2 + 0] = __floats2bfloat162_rn(v.x, v.y);
        dst[t * 2 + 1] = __floats2bfloat162_rn(v.z, v.w);
    }
}

// ============================================================================
// Prep 2: transposed bf16 weights
//   g_Wd [g][k] = (k<2048 ? Wz[k][g] : 0) - Wqz[k][g]   (k<3072)
//   g_Wzl[g][k] = Wv[k][g]                              (k<2048)
//   g_Wql[g][k] = Wqv[k][g]                             (k<3072)
// ============================================================================
__global__ void transpose_w_kernel(
    const float* __restrict__ Wz, const float* __restrict__ Wqz,
    const float* __restrict__ Wv, const float* __restrict__ Wqv) {
    __shared__ float tile[32][33];
    const int which = blockIdx.z;            // 0=d, 1=zl, 2=ql
    const int k0 = blockIdx.x * 32, g0 = blockIdx.y * 32;
    if (which == 1 && k0 >= KZ) return;
    const int tx = threadIdx.x, ty = threadIdx.y;
    for (int i = ty; i < 32; i += 8) {
        const int k = k0 + i;
        float v;
        if (which == 0)
            v = ((k < KZ) ? Wz[(size_t)k * GCOLS + g0 + tx] : 0.f)
                - Wqz[(size_t)k * GCOLS + g0 + tx];
        else if (which == 1)
            v = Wv[(size_t)k * GCOLS + g0 + tx];
        else
            v = Wqv[(size_t)k * GCOLS + g0 + tx];
        tile[i][tx] = v;
    }
    __syncthreads();
    for (int i = ty; i < 32; i += 8) {
        const __nv_bfloat16 b = __float2bfloat16(tile[tx][i]);
        if (which == 0)      g_Wd [(size_t)(g0 + i) * KQ + k0 + tx] = b;
        else if (which == 1) g_Wzl[(size_t)(g0 + i) * KZ + k0 + tx] = b;
        else                 g_Wql[(size_t)(g0 + i) * KQ + k0 + tx] = b;
    }
}

// ============================================================================
// No-op kernel: shifts gemm_kl_kernel to ncu capture slot (-s 5, 2 hidden)
// ============================================================================
__global__ void dummy_kernel() {}

// ============================================================================
// Fused triple-GEMM + KL epilogue (mma.sync bf16).
//   D  = cond @ g_Wd^T   (K=3072)
//   ZL = cond[:, :2048] @ g_Wzl^T
//   QL = cond @ g_Wql^T  (K=3072)
// grid (16 g-blocks, 128 m-tiles), 512 threads = 16 warps (4M x 4N, 16 cols/warp)
// ============================================================================
__global__ __launch_bounds__(512, 1) void gemm_kl_kernel(
    const float* __restrict__ bz, const float* __restrict__ bqz,
    const float* __restrict__ bv, const float* __restrict__ bqv) {
    extern __shared__ char dsm[];
    const uint32_t raw = smem_to_u32(dsm);
    const uint32_t sb = (raw + 1023u) & ~1023u;
    char* smc = dsm + (sb - raw);
    const int tid = threadIdx.x;
    const int lane = tid & 31;
    const int wid = tid >> 5;
    const int nb0 = blockIdx.x * BG;
    const int m0 = blockIdx.y * BM;

    float* sBD = (float*)(smc + OFF_BIAS);        // 64
    float* sBZL = sBD + 64;                       // 64
    float* sBQL = sBZL + 64;                      // 64
    if (tid < 64) {
        sBD[tid]  = bz[nb0 + tid] - bqz[nb0 + tid];
        sBZL[tid] = bv[nb0 + tid];
        sBQL[tid] = bqv[nb0 + tid];
    }

    // ---- per-lane ldmatrix address components (xor swizzle) ----
    const int wm = wid & 3;          // 4 warps along M (32 rows each)
    const int wn = wid >> 2;         // 4 warps along N (16 cols each)
    const int ar0 = wm * 32 + (lane & 15);
    const int ar1 = ar0 + 16;
    const uint32_t aoff0 = (uint32_t)ar0 * 128u, aswz0 = (uint32_t)(ar0 & 7) * 16u;
    const uint32_t aoff1 = (uint32_t)ar1 * 128u, aswz1 = (uint32_t)(ar1 & 7) * 16u;
    const uint32_t acb = (uint32_t)(lane >> 4) * 16u;
    const int brr = wn * 16 + ((lane >> 4) << 3) + (lane & 7);
    const uint32_t boff = (uint32_t)brr * 128u, bswz = (uint32_t)(brr & 7) * 16u;
    const uint32_t bcb = (uint32_t)((lane >> 3) & 1) * 16u;

    float accD[2][2][4], accZL[2][2][4], accQL[2][2][4];
#pragma unroll
    for (int i = 0; i < 2; i++)
#pragma unroll
        for (int h = 0; h < 2; h++)
#pragma unroll
            for (int c = 0; c < 4; c++) {
                accD[i][h][c] = 0.f; accZL[i][h][c] = 0.f; accQL[i][h][c] = 0.f;
            }

    // ---- async tile loader ----
    // stage layout: A @0 (16KB), Bd @16384, Bql @24576, Bzl @32768 (full only)
    auto load_stage = [&](int kt, int st) {
        const uint32_t base = sb + (uint32_t)st * STAGE_BYTES;
        const int kbyte = kt * 128;
        const bool full = (kt < NKT_Z);
        const int nch = full ? 2560 : 2048;
        for (int c = tid; c < nch; c += 512) {
            if (c < 1024) {
                const int row = c >> 3, cb = c & 7;
                const uint32_t off = (uint32_t)row * 128u +
                    (((uint32_t)cb * 16u) ^ ((uint32_t)(row & 7) * 16u));
                const char* src = (const char*)(g_cond + (size_t)(m0 + row) * KQ)
                                  + kbyte + cb * 16;
                cp16(base + off, src);
            } else {
                const int sec = (c - 1024) >> 9;       // 0=d, 1=ql, 2=zl
                const int cc = (c - 1024) & 511;
                const int row = cc >> 3, cb = cc & 7;
                const uint32_t off = (uint32_t)row * 128u +
                    (((uint32_t)cb * 16u) ^ ((uint32_t)(row & 7) * 16u));
                const char* src;
                if (sec == 0)
                    src = (const char*)(g_Wd + (size_t)(nb0 + row) * KQ) + kbyte + cb * 16;
                else if (sec == 1)
                    src = (const char*)(g_Wql + (size_t)(nb0 + row) * KQ) + kbyte + cb * 16;
                else
                    src = (const char*)(g_Wzl + (size_t)(nb0 + row) * KZ) + kbyte + cb * 16;
                cp16(base + 16384u + (uint32_t)sec * 8192u + off, src);
            }
        }
        CP_COMMIT();
    };

    load_stage(0, 0);
    load_stage(1, 1);
    load_stage(2, 2);

    for (int kt = 0; kt < NKT; kt++) {
        if (kt < NKT - 2)       { asm volatile("cp.async.wait_group 2;" ::: "memory"); }
        else if (kt == NKT - 2) { asm volatile("cp.async.wait_group 1;" ::: "memory"); }
        else                    { asm volatile("cp.async.wait_group 0;" ::: "memory"); }
        __syncthreads();
        if (kt + 3 < NKT) load_stage(kt + 3, (kt + 3) & 3);

        const uint32_t stA = sb + (uint32_t)(kt & 3) * STAGE_BYTES;
        const uint32_t stBd = stA + 16384u;
        const uint32_t stBql = stA + 24576u;
        const uint32_t stBzl = stA + 32768u;
        const bool full = (kt < NKT_Z);
#pragma unroll
        for (int ks = 0; ks < 4; ks++) {
            const uint32_t kb = (uint32_t)ks * 32u;
            uint32_t a0[4], a1[4], fd[4], fql[4];
            LDSM4(a0, stA + aoff0 + ((kb + acb) ^ aswz0));
            LDSM4(a1, stA + aoff1 + ((kb + acb) ^ aswz1));
            LDSM4(fd, stBd + boff + ((kb + bcb) ^ bswz));
            LDSM4(fql, stBql + boff + ((kb + bcb) ^ bswz));
#pragma unroll
            for (int h = 0; h < 2; h++) {
                MMA16816(accD[0][h], a0, fd[2 * h], fd[2 * h + 1]);
                MMA16816(accD[1][h], a1, fd[2 * h], fd[2 * h + 1]);
                MMA16816(accQL[0][h], a0, fql[2 * h], fql[2 * h + 1]);
                MMA16816(accQL[1][h], a1, fql[2 * h], fql[2 * h + 1]);
            }
            if (full) {
                uint32_t fzl[4];
                LDSM4(fzl, stBzl + boff + ((kb + bcb) ^ bswz));
#pragma unroll
                for (int h = 0; h < 2; h++) {
                    MMA16816(accZL[0][h], a0, fzl[2 * h], fzl[2 * h + 1]);
                    MMA16816(accZL[1][h], a1, fzl[2 * h], fzl[2 * h + 1]);
                }
            }
        }
    }

    // ---- fused KL epilogue: identical fragment layouts -> no shuffles ----
    // col = wn*16 + h*8 + (lane&3)*2 + {0,1}
    float acckl = 0.f;
#pragma unroll
    for (int mi = 0; mi < 2; mi++) {
#pragma unroll
        for (int h = 0; h < 2; h++) {
            const int col = wn * 16 + h * 8 + (lane & 3) * 2;
            const float bd0 = sBD[col], bd1 = sBD[col + 1];
            const float bl0 = sBZL[col], bl1 = sBZL[col + 1];
            const float bq0 = sBQL[col], bq1 = sBQL[col + 1];
#pragma unroll
            for (int r = 0; r < 2; r++) {
                const float d0 = accD[mi][h][2 * r] + bd0;
                const float d1 = accD[mi][h][2 * r + 1] + bd1;
                const float zl0 = accZL[mi][h][2 * r] + bl0;
                const float zl1 = accZL[mi][h][2 * r + 1] + bl1;
                const float ql0 = accQL[mi][h][2 * r] + bq0;
                const float ql1 = accQL[mi][h][2 * r + 1] + bq1;
                acckl += ql0 - zl0 + (expf(zl0) + d0 * d0) * expf(-ql0) - 1.f;
                acckl += ql1 - zl1 + (expf(zl1) + d1 * d1) * expf(-ql1) - 1.f;
            }
        }
    }

    // deterministic reduction over 16 warps
#pragma unroll
    for (int s = 16; s > 0; s >>= 1)
        acckl += __shfl_down_sync(0xFFFFFFFFu, acckl, s);
    float* red = (float*)(smc + OFF_RED);
    if (lane == 0) red[wid] = acckl;
    __syncthreads();
    if (tid == 0) {
        float s = 0.f;
        for (int w = 0; w < 16; w++) s += red[w];
        g_kl_partial[blockIdx.y * 16 + blockIdx.x] = s;
    }
}

// ============================================================================
// Small losses: cross-entropy + logic sums (one block, deterministic)
// ============================================================================
__global__ __launch_bounds__(1024) void small_loss_kernel(
    const float* __restrict__ ps, const float* __restrict__ pt,
    const float* __restrict__ pc, const int* __restrict__ labels,
    const int* __restrict__ scene, const int* __restrict__ thr) {
    __shared__ float red[1024];
    float wce = 0.f, wsum = 0.f, tsum = 0.f, vsum = 0.f;
    for (int b = threadIdx.x; b < BATCH; b += 1024) {
        const int lab = labels[b];
        const int s = scene[b], t = thr[b];
        const bool l5 = (lab == 5), l2 = (lab == 2), l3 = (lab == 3);
        const bool le = !(l5 | l2 | l3);
        const int nv = l5 ? 3 : (l2 ? 1 : (l3 ? 2 : 3));
        const int last = nv - 1;
        const float* psb = ps + (size_t)b * 6;
        const float* ptb = pt + (size_t)b * 6;
        const float* pcb = pc + (size_t)b * 6;
        #pragma unroll
        for (int slot = 0; slot < 3; slot++) {
            if (slot >= nv) break;
            int chain = l5 ? 1 : (l2 ? 0 : (l3 ? (slot == 0 ? 1 : 0)
                                               : (slot == 2 ? 0 : 1)));
            int ps_col = (!l5 && slot == last) ? s : 0;
            int pt_row = (l3 && slot == 1) ? (t == 1 ? 0 : 1) : slot;
            int pt_col = (l2 && slot == 0) ? t : ((le && slot == 2) ? t : 0);
            int pcs_col = l5 ? 1 : (slot == last ? 0 : 1);
            float PS = psb[slot * 2 + ps_col];
            float PT = ptb[pt_row * 2 + pt_col];
            float PCS = pcb[slot * 2 + pcs_col];
            float a0 = pcb[slot * 2 + 0], a1 = pcb[slot * 2 + 1];
            float mx = fmaxf(a0, a1);
            float lse = mx + logf(expf(a0 - mx) + expf(a1 - mx));
            float logp = (chain == 0 ? a0 : a1) - lse;
            float w = (chain == 0) ? 0.6f : 0.4f;
            wce += -w * logp;
            wsum += w;
            float lsig = fminf(PCS, 0.f) - log1pf(expf(-fabsf(PCS)));
            tsum += fabsf(logf(PS) + logf(PT) - lsig);
            vsum += 1.f;
        }
    }
    const int tid = threadIdx.x;
    float vals[4] = {wce, wsum, tsum, vsum};
    for (int v = 0; v < 4; v++) {
        red[tid] = vals[v];
        __syncthreads();
        for (int sft = 512; sft > 0; sft >>= 1) {
            if (tid < sft) red[tid] += red[tid + sft];
            __syncthreads();
        }
        if (tid == 0) g_small4[v] = red[0];
        __syncthreads();
    }
}

// ============================================================================
// Final combine
// ============================================================================
__global__ __launch_bounds__(1024) void combine_kernel(float* __restrict__ out) {
    __shared__ float red[1024];
    float s = 0.f;
    for (int i = threadIdx.x; i < 2048; i += 1024) s += g_kl_partial[i];
    red[threadIdx.x] = s;
    __syncthreads();
    for (int sft = 512; sft > 0; sft >>= 1) {
        if (threadIdx.x < sft) red[threadIdx.x] += red[threadIdx.x + sft];
        __syncthreads();
    }
    if (threadIdx.x == 0) {
        const float kl_loss = 0.5f * red[0] / (float)M_TOTAL;
        out[0] = g_small4[0] / g_small4[1] + kl_loss + g_small4[2] / g_small4[3];
    }
}

// ============================================================================
// kernel_launch
// ============================================================================
extern "C" void kernel_launch(void* const* d_in, const int* in_sizes, int n_in,
                              void* d_out, int out_size) {
    const float* events   = (const float*)d_in[0];
    const float* contexts = (const float*)d_in[1];
    const float* ps       = (const float*)d_in[2];
    const float* pt       = (const float*)d_in[3];
    const float* pc       = (const float*)d_in[4];
    const int*   labels   = (const int*)d_in[5];
    const int*   scene    = (const int*)d_in[6];
    const int*   thr      = (const int*)d_in[7];
    const float* Wz  = (const float*)d_in[8];
    const float* bz  = (const float*)d_in[9];
    const float* Wv  = (const float*)d_in[10];
    const float* bv  = (const float*)d_in[11];
    const float* Wqz = (const float*)d_in[12];
    const float* bqz = (const float*)d_in[13];
    const float* Wqv = (const float*)d_in[14];
    const float* bqv = (const float*)d_in[15];
    float* out = (float*)d_out;

    cudaFuncSetAttribute(gemm_kl_kernel,
                         cudaFuncAttributeMaxDynamicSharedMemorySize, SMEM_REQ);

    build_cond_kernel<<<M_TOTAL, 256>>>(events, contexts);                       // my #0
    transpose_w_kernel<<<dim3(KQ / 32, GCOLS / 32, 3), dim3(32, 8)>>>(Wz, Wqz, Wv, Wqv); // #1
    dummy_kernel<<<1, 32>>>();                                                   // #2
    gemm_kl_kernel<<<dim3(GCOLS / BG, M_TOTAL / BM), 512, SMEM_REQ>>>(bz, bqz, bv, bqv); // #3 <- ncu slot 5
    small_loss_kernel<<<1, 1024>>>(ps, pt, pc, labels, scene, thr);              // #4
    combine_kernel<<<1, 1024>>>(out);                                            // #5
}

// round 8
// speedup vs baseline: 1.6191x; 1.4621x over previous
#include <cuda_runtime.h>
#include <cuda_bf16.h>
#include <cstdint>
#include <math.h>

// ============================================================================
// Problem constants
// ============================================================================
#define HIDDEN   1024
#define BATCH    4096
#define M_TOTAL  16384          // BATCH * 4 pair rows
#define GCOLS    1024
#define KQ       3072
#define KZ       2048
#define BM       128
#define BG       64             // g-columns per CTA
#define NKT      48             // KQ / 64
#define NKT_Z    32             // KZ / 64
#define STAGE_BYTES 40960       // A 16KB + Bd 8KB + Bql 8KB + Bzl 8KB
#define OFF_BIAS (4 * STAGE_BYTES)          // 163840
#define OFF_RED  (OFF_BIAS + 768)
#define SMEM_USE (OFF_RED + 128)
#define SMEM_REQ (SMEM_USE + 1024)          // slack for manual 1KB align

// ============================================================================
// Scratch (__device__ globals; no allocation allowed)
// ============================================================================
__device__ __align__(128) __nv_bfloat16 g_cond[(size_t)M_TOTAL * KQ]; // 100 MB
__device__ __align__(128) __nv_bfloat16 g_Wd [(size_t)GCOLS * KQ];    // 6 MB  [g][k]
__device__ __align__(128) __nv_bfloat16 g_Wzl[(size_t)GCOLS * KZ];    // 4 MB
__device__ __align__(128) __nv_bfloat16 g_Wql[(size_t)GCOLS * KQ];    // 6 MB
__device__ float g_kl_partial[2048];
__device__ float g_small4[4];

// ============================================================================
// PTX helpers (baseline sm_100 ISA only: cp.async, ldmatrix, mma.sync)
// ============================================================================
__device__ __forceinline__ uint32_t smem_to_u32(const void* p) {
    uint32_t a;
    asm("{ .reg .u64 t; cvta.to.shared.u64 t, %1; cvt.u32.u64 %0, t; }" : "=r"(a) : "l"(p));
    return a;
}
__device__ __forceinline__ void cp16(uint32_t dst, const void* src) {
    asm volatile("cp.async.cg.shared.global [%0], [%1], 16;" :: "r"(dst), "l"(src) : "memory");
}
#define CP_COMMIT() asm volatile("cp.async.commit_group;" ::: "memory")

#define LDSM4(r, addr) \
    asm volatile("ldmatrix.sync.aligned.m8n8.x4.shared.b16 {%0,%1,%2,%3}, [%4];" \
        : "=r"((r)[0]), "=r"((r)[1]), "=r"((r)[2]), "=r"((r)[3]) : "r"(addr))

#define MMA16816(c, a, b0, b1) \
    asm volatile("mma.sync.aligned.m16n8k16.row.col.f32.bf16.bf16.f32 " \
        "{%0,%1,%2,%3}, {%4,%5,%6,%7}, {%8,%9}, {%0,%1,%2,%3};" \
        : "+f"((c)[0]), "+f"((c)[1]), "+f"((c)[2]), "+f"((c)[3]) \
        : "r"((a)[0]), "r"((a)[1]), "r"((a)[2]), "r"((a)[3]), \
          "r"(b0), "r"(b1))

// ============================================================================
// Prep 1: cond[16384][3072] bf16 = [events[i,s] | events[i,s+1] | contexts[i,s]]
// ============================================================================
__global__ __launch_bounds__(256) void build_cond_kernel(
    const float* __restrict__ events, const float* __restrict__ contexts) {
    const int r = blockIdx.x;                 // 0..16383
    const int i = r >> 2, s = r & 3;
    const float* e0 = events + ((size_t)i * 5 + s) * HIDDEN;
    const float* e1 = e0 + HIDDEN;
    const float* cx = contexts + ((size_t)i * 4 + s) * HIDDEN;
    __nv_bfloat162* dst = (__nv_bfloat162*)(g_cond + (size_t)r * KQ);
    for (int t = threadIdx.x; t < 768; t += 256) {     // 768 float4 = 3072 floats
        const float* src = (t < 256) ? e0 : (t < 512) ? e1 : cx;
        float4 v = *(const float4*)(src + (size_t)(t & 255) * 4);
        dst[t * 2 + 0] = __floats2bfloat162_rn(v.x, v.y);
        dst[t * 2 + 1] = __floats2bfloat162_rn(v.z, v.w);
    }
}

// ============================================================================
// Prep 2: transposed bf16 weights
//   g_Wd [g][k] = (k<2048 ? Wz[k][g] : 0) - Wqz[k][g]   (k<3072)
//   g_Wzl[g][k] = Wv[k][g]                              (k<2048)
//   g_Wql[g][k] = Wqv[k][g]                             (k<3072)
// ============================================================================
__global__ void transpose_w_kernel(
    const float* __restrict__ Wz, const float* __restrict__ Wqz,
    const float* __restrict__ Wv, const float* __restrict__ Wqv) {
    __shared__ float tile[32][33];
    const int which = blockIdx.z;            // 0=d, 1=zl, 2=ql
    const int k0 = blockIdx.x * 32, g0 = blockIdx.y * 32;
    if (which == 1 && k0 >= KZ) return;
    const int tx = threadIdx.x, ty = threadIdx.y;
    for (int i = ty; i < 32; i += 8) {
        const int k = k0 + i;
        float v;
        if (which == 0)
            v = ((k < KZ) ? Wz[(size_t)k * GCOLS + g0 + tx] : 0.f)
                - Wqz[(size_t)k * GCOLS + g0 + tx];
        else if (which == 1)
            v = Wv[(size_t)k * GCOLS + g0 + tx];
        else
            v = Wqv[(size_t)k * GCOLS + g0 + tx];
        tile[i][tx] = v;
    }
    __syncthreads();
    for (int i = ty; i < 32; i += 8) {
        const __nv_bfloat16 b = __float2bfloat16(tile[tx][i]);
        if (which == 0)      g_Wd [(size_t)(g0 + i) * KQ + k0 + tx] = b;
        else if (which == 1) g_Wzl[(size_t)(g0 + i) * KZ + k0 + tx] = b;
        else                 g_Wql[(size_t)(g0 + i) * KQ + k0 + tx] = b;
    }
}

// ============================================================================
// No-op kernel keeps gemm_kl_kernel at ncu capture slot 5
// ============================================================================
__global__ void dummy_kernel() {}

// ============================================================================
// Fused triple-GEMM + KL epilogue (mma.sync bf16, ILP-pipelined fragments).
// grid (16 g-blocks, 128 m-tiles), 256 threads = 8 warps (2M x 4N).
// Each warp: 64 rows x 16 cols x 3 matrices; fragments double-buffered in regs.
// ============================================================================
__global__ __launch_bounds__(256, 1) void gemm_kl_kernel(
    const float* __restrict__ bz, const float* __restrict__ bqz,
    const float* __restrict__ bv, const float* __restrict__ bqv) {
    extern __shared__ char dsm[];
    const uint32_t raw = smem_to_u32(dsm);
    const uint32_t sb = (raw + 1023u) & ~1023u;
    char* smc = dsm + (sb - raw);
    const int tid = threadIdx.x;
    const int lane = tid & 31;
    const int wid = tid >> 5;
    const int nb0 = blockIdx.x * BG;
    const int m0 = blockIdx.y * BM;

    float* sBD = (float*)(smc + OFF_BIAS);        // 64
    float* sBZL = sBD + 64;                       // 64
    float* sBQL = sBZL + 64;                      // 64
    if (tid < 64) {
        sBD[tid]  = bz[nb0 + tid] - bqz[nb0 + tid];
        sBZL[tid] = bv[nb0 + tid];
        sBQL[tid] = bqv[nb0 + tid];
    }

    // ---- per-lane ldmatrix address components (xor swizzle) ----
    const int wm = wid & 1;          // 2 warps along M (64 rows each)
    const int wn = wid >> 1;         // 4 warps along N (16 cols each)
    const uint32_t aswz = (uint32_t)(lane & 7) * 16u;
    const uint32_t acb = (uint32_t)(lane >> 4) * 16u;
    uint32_t aoff[4];
#pragma unroll
    for (int p = 0; p < 4; p++)
        aoff[p] = (uint32_t)(wm * 64 + p * 16 + (lane & 15)) * 128u;
    const int brr = wn * 16 + ((lane >> 4) << 3) + (lane & 7);
    const uint32_t boff = (uint32_t)brr * 128u;
    const uint32_t bswz = (uint32_t)(lane & 7) * 16u;
    const uint32_t bcb = (uint32_t)((lane >> 3) & 1) * 16u;

    // ---- accumulators: [p=4 m-frags][h=2 n-halves][4] per matrix ----
    float accD[4][2][4], accZL[4][2][4], accQL[4][2][4];
#pragma unroll
    for (int p = 0; p < 4; p++)
#pragma unroll
        for (int h = 0; h < 2; h++)
#pragma unroll
            for (int c = 0; c < 4; c++) {
                accD[p][h][c] = 0.f; accZL[p][h][c] = 0.f; accQL[p][h][c] = 0.f;
            }

    // ---- precomputed loader addressing (static per thread across kt) ----
    // 2560 chunks/stage: [0,1024)=A, [1024,1536)=Bd, [1536,2048)=Bql, [2048,2560)=Bzl
    uint32_t dstoff[10];
    const char* srcp[10];
#pragma unroll
    for (int it = 0; it < 10; it++) {
        const int c = tid + it * 256;
        const int cb = c & 7;
        if (c < 1024) {
            const int row = c >> 3;
            dstoff[it] = (uint32_t)(row * 128 + cb * 16) ^ ((uint32_t)(row & 7) * 16u);
            srcp[it] = (const char*)(g_cond + (size_t)(m0 + row) * KQ) + cb * 16;
        } else if (c < 1536) {
            const int row = (c - 1024) >> 3;
            dstoff[it] = 16384u + ((uint32_t)(row * 128 + cb * 16) ^ ((uint32_t)(row & 7) * 16u));
            srcp[it] = (const char*)(g_Wd + (size_t)(nb0 + row) * KQ) + cb * 16;
        } else if (c < 2048) {
            const int row = (c - 1536) >> 3;
            dstoff[it] = 24576u + ((uint32_t)(row * 128 + cb * 16) ^ ((uint32_t)(row & 7) * 16u));
            srcp[it] = (const char*)(g_Wql + (size_t)(nb0 + row) * KQ) + cb * 16;
        } else {
            const int row = (c - 2048) >> 3;
            dstoff[it] = 32768u + ((uint32_t)(row * 128 + cb * 16) ^ ((uint32_t)(row & 7) * 16u));
            srcp[it] = (const char*)(g_Wzl + (size_t)(nb0 + row) * KZ) + cb * 16;
        }
    }

#define LOAD_STAGE(kt) do { \
        const uint32_t _base = sb + (uint32_t)((kt) & 3) * STAGE_BYTES; \
        const int _kb = (kt) * 128; \
        _Pragma("unroll") \
        for (int _it = 0; _it < 8; _it++) cp16(_base + dstoff[_it], srcp[_it] + _kb); \
        if ((kt) < NKT_Z) { \
            cp16(_base + dstoff[8], srcp[8] + _kb); \
            cp16(_base + dstoff[9], srcp[9] + _kb); \
        } \
        CP_COMMIT(); \
    } while (0)

    LOAD_STAGE(0);
    LOAD_STAGE(1);
    LOAD_STAGE(2);

    // ---- fragment double buffers ----
    uint32_t aF[2][4][4], fdF[2][4], fqlF[2][4], fzlF[2][4];

#define LDFRAG(buf, ks, stA, full) do { \
        const uint32_t _ka = (((uint32_t)(ks) * 32u + acb) ^ aswz); \
        const uint32_t _kb = (((uint32_t)(ks) * 32u + bcb) ^ bswz); \
        LDSM4(aF[buf][0], (stA) + aoff[0] + _ka); \
        LDSM4(aF[buf][1], (stA) + aoff[1] + _ka); \
        LDSM4(aF[buf][2], (stA) + aoff[2] + _ka); \
        LDSM4(aF[buf][3], (stA) + aoff[3] + _ka); \
        LDSM4(fdF[buf],  (stA) + 16384u + boff + _kb); \
        LDSM4(fqlF[buf], (stA) + 24576u + boff + _kb); \
        if (full) LDSM4(fzlF[buf], (stA) + 32768u + boff + _kb); \
    } while (0)

#define DOMMA(buf, full) do { \
        _Pragma("unroll") \
        for (int _p = 0; _p < 4; _p++) { \
            _Pragma("unroll") \
            for (int _h = 0; _h < 2; _h++) { \
                MMA16816(accD[_p][_h],  aF[buf][_p], fdF[buf][2*_h],  fdF[buf][2*_h+1]); \
                MMA16816(accQL[_p][_h], aF[buf][_p], fqlF[buf][2*_h], fqlF[buf][2*_h+1]); \
            } \
        } \
        if (full) { \
            _Pragma("unroll") \
            for (int _p = 0; _p < 4; _p++) { \
                _Pragma("unroll") \
                for (int _h = 0; _h < 2; _h++) \
                    MMA16816(accZL[_p][_h], aF[buf][_p], fzlF[buf][2*_h], fzlF[buf][2*_h+1]); \
            } \
        } \
    } while (0)

    for (int kt = 0; kt < NKT; kt++) {
        if (kt < NKT - 2)       { asm volatile("cp.async.wait_group 2;" ::: "memory"); }
        else if (kt == NKT - 2) { asm volatile("cp.async.wait_group 1;" ::: "memory"); }
        else                    { asm volatile("cp.async.wait_group 0;" ::: "memory"); }
        __syncthreads();
        const uint32_t stA = sb + (uint32_t)(kt & 3) * STAGE_BYTES;
        const bool full = (kt < NKT_Z);

        LDFRAG(0, 0, stA, full);
        if (kt + 3 < NKT) LOAD_STAGE(kt + 3);
        LDFRAG(1, 1, stA, full);
        DOMMA(0, full);
        LDFRAG(0, 2, stA, full);
        DOMMA(1, full);
        LDFRAG(1, 3, stA, full);
        DOMMA(0, full);
        DOMMA(1, full);
    }

    // ---- fused KL epilogue: identical fragment layouts -> no shuffles ----
    // col = wn*16 + h*8 + (lane&3)*2 + {0,1}
    float acckl = 0.f;
#pragma unroll
    for (int p = 0; p < 4; p++) {
#pragma unroll
        for (int h = 0; h < 2; h++) {
            const int col = wn * 16 + h * 8 + (lane & 3) * 2;
            const float bd0 = sBD[col], bd1 = sBD[col + 1];
            const float bl0 = sBZL[col], bl1 = sBZL[col + 1];
            const float bq0 = sBQL[col], bq1 = sBQL[col + 1];
#pragma unroll
            for (int r = 0; r < 2; r++) {
                const float d0 = accD[p][h][2 * r] + bd0;
                const float d1 = accD[p][h][2 * r + 1] + bd1;
                const float zl0 = accZL[p][h][2 * r] + bl0;
                const float zl1 = accZL[p][h][2 * r + 1] + bl1;
                const float ql0 = accQL[p][h][2 * r] + bq0;
                const float ql1 = accQL[p][h][2 * r + 1] + bq1;
                acckl += ql0 - zl0 + (expf(zl0) + d0 * d0) * expf(-ql0) - 1.f;
                acckl += ql1 - zl1 + (expf(zl1) + d1 * d1) * expf(-ql1) - 1.f;
            }
        }
    }

    // deterministic reduction over 8 warps
#pragma unroll
    for (int s = 16; s > 0; s >>= 1)
        acckl += __shfl_down_sync(0xFFFFFFFFu, acckl, s);
    float* red = (float*)(smc + OFF_RED);
    if (lane == 0) red[wid] = acckl;
    __syncthreads();
    if (tid == 0) {
        float s = 0.f;
        for (int w = 0; w < 8; w++) s += red[w];
        g_kl_partial[blockIdx.y * 16 + blockIdx.x] = s;
    }
}

// ============================================================================
// Small losses: cross-entropy + logic sums (one block, deterministic)
// ============================================================================
__global__ __launch_bounds__(1024) void small_loss_kernel(
    const float* __restrict__ ps, const float* __restrict__ pt,
    const float* __restrict__ pc, const int* __restrict__ labels,
    const int* __restrict__ scene, const int* __restrict__ thr) {
    __shared__ float red[1024];
    float wce = 0.f, wsum = 0.f, tsum = 0.f, vsum = 0.f;
    for (int b = threadIdx.x; b < BATCH; b += 1024) {
        const int lab = labels[b];
        const int s = scene[b], t = thr[b];
        const bool l5 = (lab == 5), l2 = (lab == 2), l3 = (lab == 3);
        const bool le = !(l5 | l2 | l3);
        const int nv = l5 ? 3 : (l2 ? 1 : (l3 ? 2 : 3));
        const int last = nv - 1;
        const float* psb = ps + (size_t)b * 6;
        const float* ptb = pt + (size_t)b * 6;
        const float* pcb = pc + (size_t)b * 6;
        #pragma unroll
        for (int slot = 0; slot < 3; slot++) {
            if (slot >= nv) break;
            int chain = l5 ? 1 : (l2 ? 0 : (l3 ? (slot == 0 ? 1 : 0)
                                               : (slot == 2 ? 0 : 1)));
            int ps_col = (!l5 && slot == last) ? s : 0;
            int pt_row = (l3 && slot == 1) ? (t == 1 ? 0 : 1) : slot;
            int pt_col = (l2 && slot == 0) ? t : ((le && slot == 2) ? t : 0);
            int pcs_col = l5 ? 1 : (slot == last ? 0 : 1);
            float PS = psb[slot * 2 + ps_col];
            float PT = ptb[pt_row * 2 + pt_col];
            float PCS = pcb[slot * 2 + pcs_col];
            float a0 = pcb[slot * 2 + 0], a1 = pcb[slot * 2 + 1];
            float mx = fmaxf(a0, a1);
            float lse = mx + logf(expf(a0 - mx) + expf(a1 - mx));
            float logp = (chain == 0 ? a0 : a1) - lse;
            float w = (chain == 0) ? 0.6f : 0.4f;
            wce += -w * logp;
            wsum += w;
            float lsig = fminf(PCS, 0.f) - log1pf(expf(-fabsf(PCS)));
            tsum += fabsf(logf(PS) + logf(PT) - lsig);
            vsum += 1.f;
        }
    }
    const int tid = threadIdx.x;
    float vals[4] = {wce, wsum, tsum, vsum};
    for (int v = 0; v < 4; v++) {
        red[tid] = vals[v];
        __syncthreads();
        for (int sft = 512; sft > 0; sft >>= 1) {
            if (tid < sft) red[tid] += red[tid + sft];
            __syncthreads();
        }
        if (tid == 0) g_small4[v] = red[0];
        __syncthreads();
    }
}

// ============================================================================
// Final combine
// ============================================================================
__global__ __launch_bounds__(1024) void combine_kernel(float* __restrict__ out) {
    __shared__ float red[1024];
    float s = 0.f;
    for (int i = threadIdx.x; i < 2048; i += 1024) s += g_kl_partial[i];
    red[threadIdx.x] = s;
    __syncthreads();
    for (int sft = 512; sft > 0; sft >>= 1) {
        if (threadIdx.x < sft) red[threadIdx.x] += red[threadIdx.x + sft];
        __syncthreads();
    }
    if (threadIdx.x == 0) {
        const float kl_loss = 0.5f * red[0] / (float)M_TOTAL;
        out[0] = g_small4[0] / g_small4[1] + kl_loss + g_small4[2] / g_small4[3];
    }
}

// ============================================================================
// kernel_launch
// ============================================================================
extern "C" void kernel_launch(void* const* d_in, const int* in_sizes, int n_in,
                              void* d_out, int out_size) {
    const float* events   = (const float*)d_in[0];
    const float* contexts = (const float*)d_in[1];
    const float* ps       = (const float*)d_in[2];
    const float* pt       = (const float*)d_in[3];
    const float* pc       = (const float*)d_in[4];
    const int*   labels   = (const int*)d_in[5];
    const int*   scene    = (const int*)d_in[6];
    const int*   thr      = (const int*)d_in[7];
    const float* Wz  = (const float*)d_in[8];
    const float* bz  = (const float*)d_in[9];
    const float* Wv  = (const float*)d_in[10];
    const float* bv  = (const float*)d_in[11];
    const float* Wqz = (const float*)d_in[12];
    const float* bqz = (const float*)d_in[13];
    const float* Wqv = (const float*)d_in[14];
    const float* bqv = (const float*)d_in[15];
    float* out = (float*)d_out;

    cudaFuncSetAttribute(gemm_kl_kernel,
                         cudaFuncAttributeMaxDynamicSharedMemorySize, SMEM_REQ);

    build_cond_kernel<<<M_TOTAL, 256>>>(events, contexts);                       // my #0
    transpose_w_kernel<<<dim3(KQ / 32, GCOLS / 32, 3), dim3(32, 8)>>>(Wz, Wqz, Wv, Wqv); // #1
    dummy_kernel<<<1, 32>>>();                                                   // #2
    gemm_kl_kernel<<<dim3(GCOLS / BG, M_TOTAL / BM), 256, SMEM_REQ>>>(bz, bqz, bv, bqv); // #3 <- ncu slot 5
    small_loss_kernel<<<1, 1024>>>(ps, pt, pc, labels, scene, thr);              // #4
    combine_kernel<<<1, 1024>>>(out);                                            // #5
}

// round 10
// speedup vs baseline: 1.7250x; 1.0654x over previous
#include <cuda_runtime.h>
#include <cuda_bf16.h>
#include <cstdint>
#include <math.h>

// ============================================================================
// Problem constants
// ============================================================================
#define HIDDEN   1024
#define BATCH    4096
#define M_TOTAL  16384          // BATCH * 4 pair rows
#define GCOLS    1024
#define KQ       3072
#define KZ       2048
#define BM       128
#define BG       64             // g-columns per CTA
#define NKT      48             // KQ / 64
#define NKT_Z    32             // KZ / 64
#define STAGE_BYTES 40960       // A 16KB + Bd 8KB + Bql 8KB + Bzl 8KB
#define OFF_BIAS (4 * STAGE_BYTES)          // 163840
#define OFF_RED  (OFF_BIAS + 768)
#define SMEM_USE (OFF_RED + 128)
#define SMEM_REQ (SMEM_USE + 1024)          // slack for manual 1KB align
#define SL_BLOCKS 32

// ============================================================================
// Scratch (__device__ globals; no allocation allowed)
// ============================================================================
__device__ __align__(128) __nv_bfloat16 g_cond[(size_t)M_TOTAL * KQ]; // 100 MB
__device__ __align__(128) __nv_bfloat16 g_Wd [(size_t)GCOLS * KQ];    // 6 MB  [g][k]
__device__ __align__(128) __nv_bfloat16 g_Wzl[(size_t)GCOLS * KZ];    // 4 MB
__device__ __align__(128) __nv_bfloat16 g_Wql[(size_t)GCOLS * KQ];    // 6 MB
__device__ float g_kl_partial[2048];
__device__ float g_small_partial[SL_BLOCKS * 4];

// ============================================================================
// PTX helpers (baseline sm_100 ISA only: cp.async, ldmatrix, mma.sync)
// ============================================================================
__device__ __forceinline__ uint32_t smem_to_u32(const void* p) {
    uint32_t a;
    asm("{ .reg .u64 t; cvta.to.shared.u64 t, %1; cvt.u32.u64 %0, t; }" : "=r"(a) : "l"(p));
    return a;
}
__device__ __forceinline__ void cp16(uint32_t dst, const void* src) {
    asm volatile("cp.async.cg.shared.global [%0], [%1], 16;" :: "r"(dst), "l"(src) : "memory");
}
#define CP_COMMIT() asm volatile("cp.async.commit_group;" ::: "memory")

#define LDSM4(r, addr) \
    asm volatile("ldmatrix.sync.aligned.m8n8.x4.shared.b16 {%0,%1,%2,%3}, [%4];" \
        : "=r"((r)[0]), "=r"((r)[1]), "=r"((r)[2]), "=r"((r)[3]) : "r"(addr))

#define MMA16816(c, a, b0, b1) \
    asm volatile("mma.sync.aligned.m16n8k16.row.col.f32.bf16.bf16.f32 " \
        "{%0,%1,%2,%3}, {%4,%5,%6,%7}, {%8,%9}, {%0,%1,%2,%3};" \
        : "+f"((c)[0]), "+f"((c)[1]), "+f"((c)[2]), "+f"((c)[3]) \
        : "r"((a)[0]), "r"((a)[1]), "r"((a)[2]), "r"((a)[3]), \
          "r"(b0), "r"(b1))

// ============================================================================
// Prep 1: cond[16384][3072] bf16 = [events[i,s] | events[i,s+1] | contexts[i,s]]
// ============================================================================
__global__ __launch_bounds__(256) void build_cond_kernel(
    const float* __restrict__ events, const float* __restrict__ contexts) {
    const int r = blockIdx.x;                 // 0..16383
    const int i = r >> 2, s = r & 3;
    const float* e0 = events + ((size_t)i * 5 + s) * HIDDEN;
    const float* e1 = e0 + HIDDEN;
    const float* cx = contexts + ((size_t)i * 4 + s) * HIDDEN;
    __nv_bfloat162* dst = (__nv_bfloat162*)(g_cond + (size_t)r * KQ);
    for (int t = threadIdx.x; t < 768; t += 256) {     // 768 float4 = 3072 floats
        const float* src = (t < 256) ? e0 : (t < 512) ? e1 : cx;
        float4 v = *(const float4*)(src + (size_t)(t & 255) * 4);
        dst[t * 2 + 0] = __floats2bfloat162_rn(v.x, v.y);
        dst[t * 2 + 1] = __floats2bfloat162_rn(v.z, v.w);
    }
}

// ============================================================================
// Prep 2: transposed bf16 weights
//   g_Wd [g][k] = (k<2048 ? Wz[k][g] : 0) - Wqz[k][g]   (k<3072)
//   g_Wzl[g][k] = Wv[k][g]                              (k<2048)
//   g_Wql[g][k] = Wqv[k][g]                             (k<3072)
// ============================================================================
__global__ void transpose_w_kernel(
    const float* __restrict__ Wz, const float* __restrict__ Wqz,
    const float* __restrict__ Wv, const float* __restrict__ Wqv) {
    __shared__ float tile[32][33];
    const int which = blockIdx.z;            // 0=d, 1=zl, 2=ql
    const int k0 = blockIdx.x * 32, g0 = blockIdx.y * 32;
    if (which == 1 && k0 >= KZ) return;
    const int tx = threadIdx.x, ty = threadIdx.y;
    for (int i = ty; i < 32; i += 8) {
        const int k = k0 + i;
        float v;
        if (which == 0)
            v = ((k < KZ) ? Wz[(size_t)k * GCOLS + g0 + tx] : 0.f)
                - Wqz[(size_t)k * GCOLS + g0 + tx];
        else if (which == 1)
            v = Wv[(size_t)k * GCOLS + g0 + tx];
        else
            v = Wqv[(size_t)k * GCOLS + g0 + tx];
        tile[i][tx] = v;
    }
    __syncthreads();
    for (int i = ty; i < 32; i += 8) {
        const __nv_bfloat16 b = __float2bfloat16(tile[tx][i]);
        if (which == 0)      g_Wd [(size_t)(g0 + i) * KQ + k0 + tx] = b;
        else if (which == 1) g_Wzl[(size_t)(g0 + i) * KZ + k0 + tx] = b;
        else                 g_Wql[(size_t)(g0 + i) * KQ + k0 + tx] = b;
    }
}

// ============================================================================
// No-op kernel keeps gemm_kl_kernel at ncu capture slot 5
// ============================================================================
__global__ void dummy_kernel() {}

// ============================================================================
// Fused triple-GEMM + KL epilogue (mma.sync bf16, cross-kt fragment prefetch).
// grid (16 g-blocks, 128 m-tiles), 256 threads = 8 warps (2M x 4N).
// ============================================================================
__global__ __launch_bounds__(256, 1) void gemm_kl_kernel(
    const float* __restrict__ bz, const float* __restrict__ bqz,
    const float* __restrict__ bv, const float* __restrict__ bqv) {
    extern __shared__ char dsm[];
    const uint32_t raw = smem_to_u32(dsm);
    const uint32_t sb = (raw + 1023u) & ~1023u;
    char* smc = dsm + (sb - raw);
    const int tid = threadIdx.x;
    const int lane = tid & 31;
    const int wid = tid >> 5;
    const int nb0 = blockIdx.x * BG;
    const int m0 = blockIdx.y * BM;

    float* sBD = (float*)(smc + OFF_BIAS);        // 64
    float* sBZL = sBD + 64;                       // 64
    float* sBQL = sBZL + 64;                      // 64
    if (tid < 64) {
        sBD[tid]  = bz[nb0 + tid] - bqz[nb0 + tid];
        sBZL[tid] = bv[nb0 + tid];
        sBQL[tid] = bqv[nb0 + tid];
    }

    // ---- per-lane ldmatrix address components (xor swizzle) ----
    const int wm = wid & 1;          // 2 warps along M (64 rows each)
    const int wn = wid >> 1;         // 4 warps along N (16 cols each)
    const uint32_t aswz = (uint32_t)(lane & 7) * 16u;
    const uint32_t acb = (uint32_t)(lane >> 4) * 16u;
    uint32_t aoff[4];
#pragma unroll
    for (int p = 0; p < 4; p++)
        aoff[p] = (uint32_t)(wm * 64 + p * 16 + (lane & 15)) * 128u;
    const int brr = wn * 16 + ((lane >> 4) << 3) + (lane & 7);
    const uint32_t boff = (uint32_t)brr * 128u;
    const uint32_t bswz = (uint32_t)(lane & 7) * 16u;
    const uint32_t bcb = (uint32_t)((lane >> 3) & 1) * 16u;

    // ---- accumulators: [p=4 m-frags][h=2 n-halves][4] per matrix ----
    float accD[4][2][4], accZL[4][2][4], accQL[4][2][4];
#pragma unroll
    for (int p = 0; p < 4; p++)
#pragma unroll
        for (int h = 0; h < 2; h++)
#pragma unroll
            for (int c = 0; c < 4; c++) {
                accD[p][h][c] = 0.f; accZL[p][h][c] = 0.f; accQL[p][h][c] = 0.f;
            }

    // ---- precomputed loader addressing (static per thread across kt) ----
    uint32_t dstoff[10];
    const char* srcp[10];
#pragma unroll
    for (int it = 0; it < 10; it++) {
        const int c = tid + it * 256;
        const int cb = c & 7;
        if (c < 1024) {
            const int row = c >> 3;
            dstoff[it] = (uint32_t)(row * 128 + cb * 16) ^ ((uint32_t)(row & 7) * 16u);
            srcp[it] = (const char*)(g_cond + (size_t)(m0 + row) * KQ) + cb * 16;
        } else if (c < 1536) {
            const int row = (c - 1024) >> 3;
            dstoff[it] = 16384u + ((uint32_t)(row * 128 + cb * 16) ^ ((uint32_t)(row & 7) * 16u));
            srcp[it] = (const char*)(g_Wd + (size_t)(nb0 + row) * KQ) + cb * 16;
        } else if (c < 2048) {
            const int row = (c - 1536) >> 3;
            dstoff[it] = 24576u + ((uint32_t)(row * 128 + cb * 16) ^ ((uint32_t)(row & 7) * 16u));
            srcp[it] = (const char*)(g_Wql + (size_t)(nb0 + row) * KQ) + cb * 16;
        } else {
            const int row = (c - 2048) >> 3;
            dstoff[it] = 32768u + ((uint32_t)(row * 128 + cb * 16) ^ ((uint32_t)(row & 7) * 16u));
            srcp[it] = (const char*)(g_Wzl + (size_t)(nb0 + row) * KZ) + cb * 16;
        }
    }

#define LOAD_STAGE(kt) do { \
        const uint32_t _base = sb + (uint32_t)((kt) & 3) * STAGE_BYTES; \
        const int _kb = (kt) * 128; \
        _Pragma("unroll") \
        for (int _it = 0; _it < 8; _it++) cp16(_base + dstoff[_it], srcp[_it] + _kb); \
        if ((kt) < NKT_Z) { \
            cp16(_base + dstoff[8], srcp[8] + _kb); \
            cp16(_base + dstoff[9], srcp[9] + _kb); \
        } \
        CP_COMMIT(); \
    } while (0)

    // ---- fragment double buffers ----
    uint32_t aF[2][4][4], fdF[2][4], fqlF[2][4], fzlF[2][4];

#define LDFRAG(buf, ks, stA, full) do { \
        const uint32_t _ka = (((uint32_t)(ks) * 32u + acb) ^ aswz); \
        const uint32_t _kb = (((uint32_t)(ks) * 32u + bcb) ^ bswz); \
        LDSM4(aF[buf][0], (stA) + aoff[0] + _ka); \
        LDSM4(aF[buf][1], (stA) + aoff[1] + _ka); \
        LDSM4(aF[buf][2], (stA) + aoff[2] + _ka); \
        LDSM4(aF[buf][3], (stA) + aoff[3] + _ka); \
        LDSM4(fdF[buf],  (stA) + 16384u + boff + _kb); \
        LDSM4(fqlF[buf], (stA) + 24576u + boff + _kb); \
        if (full) LDSM4(fzlF[buf], (stA) + 32768u + boff + _kb); \
    } while (0)

#define DOMMA(buf, full) do { \
        _Pragma("unroll") \
        for (int _p = 0; _p < 4; _p++) { \
            _Pragma("unroll") \
            for (int _h = 0; _h < 2; _h++) { \
                MMA16816(accD[_p][_h],  aF[buf][_p], fdF[buf][2*_h],  fdF[buf][2*_h+1]); \
                MMA16816(accQL[_p][_h], aF[buf][_p], fqlF[buf][2*_h], fqlF[buf][2*_h+1]); \
            } \
        } \
        if (full) { \
            _Pragma("unroll") \
            for (int _p = 0; _p < 4; _p++) { \
                _Pragma("unroll") \
                for (int _h = 0; _h < 2; _h++) \
                    MMA16816(accZL[_p][_h], aF[buf][_p], fzlF[buf][2*_h], fzlF[buf][2*_h+1]); \
            } \
        } \
    } while (0)

    // ---- prologue: 3 stages in flight, prefetch ks0 of stage 0 ----
    LOAD_STAGE(0);
    LOAD_STAGE(1);
    LOAD_STAGE(2);
    asm volatile("cp.async.wait_group 2;" ::: "memory");
    __syncthreads();
    LDFRAG(0, 0, sb, true);

    for (int kt = 0; kt < NKT; kt++) {
        const uint32_t stA = sb + (uint32_t)(kt & 3) * STAGE_BYTES;
        const bool full = (kt < NKT_Z);
        // buf0 already holds ks0 fragments (prefetched)
        LDFRAG(1, 1, stA, full);
        if (kt + 3 < NKT) LOAD_STAGE(kt + 3);
        DOMMA(0, full);
        LDFRAG(0, 2, stA, full);
        DOMMA(1, full);
        LDFRAG(1, 3, stA, full);
        DOMMA(0, full);
        if (kt < NKT - 1) {
            // stage kt+1 fully resident after this wait+barrier
            if (kt <= NKT - 4)      { asm volatile("cp.async.wait_group 2;" ::: "memory"); }
            else if (kt == NKT - 3) { asm volatile("cp.async.wait_group 1;" ::: "memory"); }
            else                    { asm volatile("cp.async.wait_group 0;" ::: "memory"); }
            __syncthreads();
            const uint32_t stN = sb + (uint32_t)((kt + 1) & 3) * STAGE_BYTES;
            const bool fulln = (kt + 1 < NKT_Z);
            LDFRAG(0, 0, stN, fulln);     // prefetch next kt's ks0
        }
        DOMMA(1, full);
    }

    // ---- fused KL epilogue: identical fragment layouts -> no shuffles ----
    float acckl = 0.f;
#pragma unroll
    for (int p = 0; p < 4; p++) {
#pragma unroll
        for (int h = 0; h < 2; h++) {
            const int col = wn * 16 + h * 8 + (lane & 3) * 2;
            const float bd0 = sBD[col], bd1 = sBD[col + 1];
            const float bl0 = sBZL[col], bl1 = sBZL[col + 1];
            const float bq0 = sBQL[col], bq1 = sBQL[col + 1];
#pragma unroll
            for (int r = 0; r < 2; r++) {
                const float d0 = accD[p][h][2 * r] + bd0;
                const float d1 = accD[p][h][2 * r + 1] + bd1;
                const float zl0 = accZL[p][h][2 * r] + bl0;
                const float zl1 = accZL[p][h][2 * r + 1] + bl1;
                const float ql0 = accQL[p][h][2 * r] + bq0;
                const float ql1 = accQL[p][h][2 * r + 1] + bq1;
                acckl += ql0 - zl0 + (expf(zl0) + d0 * d0) * expf(-ql0) - 1.f;
                acckl += ql1 - zl1 + (expf(zl1) + d1 * d1) * expf(-ql1) - 1.f;
            }
        }
    }

    // deterministic reduction over 8 warps
#pragma unroll
    for (int s = 16; s > 0; s >>= 1)
        acckl += __shfl_down_sync(0xFFFFFFFFu, acckl, s);
    float* red = (float*)(smc + OFF_RED);
    if (lane == 0) red[wid] = acckl;
    __syncthreads();
    if (tid == 0) {
        float s = 0.f;
        for (int w = 0; w < 8; w++) s += red[w];
        g_kl_partial[blockIdx.y * 16 + blockIdx.x] = s;
    }
}

// ============================================================================
// Small losses: 32 blocks x 128 threads, one batch element each
// ============================================================================
__global__ __launch_bounds__(128) void small_loss_kernel(
    const float* __restrict__ ps, const float* __restrict__ pt,
    const float* __restrict__ pc, const int* __restrict__ labels,
    const int* __restrict__ scene, const int* __restrict__ thr) {
    __shared__ float red[128];
    const int b = blockIdx.x * 128 + threadIdx.x;    // < 4096
    float wce = 0.f, wsum = 0.f, tsum = 0.f, vsum = 0.f;
    {
        const int lab = labels[b];
        const int s = scene[b], t = thr[b];
        const bool l5 = (lab == 5), l2 = (lab == 2), l3 = (lab == 3);
        const bool le = !(l5 | l2 | l3);
        const int nv = l5 ? 3 : (l2 ? 1 : (l3 ? 2 : 3));
        const int last = nv - 1;
        const float* psb = ps + (size_t)b * 6;
        const float* ptb = pt + (size_t)b * 6;
        const float* pcb = pc + (size_t)b * 6;
        #pragma unroll
        for (int slot = 0; slot < 3; slot++) {
            if (slot >= nv) break;
            int chain = l5 ? 1 : (l2 ? 0 : (l3 ? (slot == 0 ? 1 : 0)
                                               : (slot == 2 ? 0 : 1)));
            int ps_col = (!l5 && slot == last) ? s : 0;
            int pt_row = (l3 && slot == 1) ? (t == 1 ? 0 : 1) : slot;
            int pt_col = (l2 && slot == 0) ? t : ((le && slot == 2) ? t : 0);
            int pcs_col = l5 ? 1 : (slot == last ? 0 : 1);
            float PS = psb[slot * 2 + ps_col];
            float PT = ptb[pt_row * 2 + pt_col];
            float PCS = pcb[slot * 2 + pcs_col];
            float a0 = pcb[slot * 2 + 0], a1 = pcb[slot * 2 + 1];
            float mx = fmaxf(a0, a1);
            float lse = mx + logf(expf(a0 - mx) + expf(a1 - mx));
            float logp = (chain == 0 ? a0 : a1) - lse;
            float w = (chain == 0) ? 0.6f : 0.4f;
            wce += -w * logp;
            wsum += w;
            float lsig = fminf(PCS, 0.f) - log1pf(expf(-fabsf(PCS)));
            tsum += fabsf(logf(PS) + logf(PT) - lsig);
            vsum += 1.f;
        }
    }
    const int tid = threadIdx.x;
    float vals[4] = {wce, wsum, tsum, vsum};
    for (int v = 0; v < 4; v++) {
        red[tid] = vals[v];
        __syncthreads();
        for (int sft = 64; sft > 0; sft >>= 1) {
            if (tid < sft) red[tid] += red[tid + sft];
            __syncthreads();
        }
        if (tid == 0) g_small_partial[blockIdx.x * 4 + v] = red[0];
        __syncthreads();
    }
}

// ============================================================================
// Final combine
// ============================================================================
__global__ __launch_bounds__(1024) void combine_kernel(float* __restrict__ out) {
    __shared__ float red[1024];
    float s = 0.f;
    for (int i = threadIdx.x; i < 2048; i += 1024) s += g_kl_partial[i];
    red[threadIdx.x] = s;
    __syncthreads();
    for (int sft = 512; sft > 0; sft >>= 1) {
        if (threadIdx.x < sft) red[threadIdx.x] += red[threadIdx.x + sft];
        __syncthreads();
    }
    if (threadIdx.x == 0) {
        float sm[4] = {0.f, 0.f, 0.f, 0.f};
        for (int bi = 0; bi < SL_BLOCKS; bi++)
            for (int v = 0; v < 4; v++) sm[v] += g_small_partial[bi * 4 + v];
        const float kl_loss = 0.5f * red[0] / (float)M_TOTAL;
        out[0] = sm[0] / sm[1] + kl_loss + sm[2] / sm[3];
    }
}

// ============================================================================
// kernel_launch
// ============================================================================
extern "C" void kernel_launch(void* const* d_in, const int* in_sizes, int n_in,
                              void* d_out, int out_size) {
    const float* events   = (const float*)d_in[0];
    const float* contexts = (const float*)d_in[1];
    const float* ps       = (const float*)d_in[2];
    const float* pt       = (const float*)d_in[3];
    const float* pc       = (const float*)d_in[4];
    const int*   labels   = (const int*)d_in[5];
    const int*   scene    = (const int*)d_in[6];
    const int*   thr      = (const int*)d_in[7];
    const float* Wz  = (const float*)d_in[8];
    const float* bz  = (const float*)d_in[9];
    const float* Wv  = (const float*)d_in[10];
    const float* bv  = (const float*)d_in[11];
    const float* Wqz = (const float*)d_in[12];
    const float* bqz = (const float*)d_in[13];
    const float* Wqv = (const float*)d_in[14];
    const float* bqv = (const float*)d_in[15];
    float* out = (float*)d_out;

    cudaFuncSetAttribute(gemm_kl_kernel,
                         cudaFuncAttributeMaxDynamicSharedMemorySize, SMEM_REQ);

    build_cond_kernel<<<M_TOTAL, 256>>>(events, contexts);                       // my #0
    transpose_w_kernel<<<dim3(KQ / 32, GCOLS / 32, 3), dim3(32, 8)>>>(Wz, Wqz, Wv, Wqv); // #1
    dummy_kernel<<<1, 32>>>();                                                   // #2
    gemm_kl_kernel<<<dim3(GCOLS / BG, M_TOTAL / BM), 256, SMEM_REQ>>>(bz, bqz, bv, bqv); // #3 <- ncu slot 5
    small_loss_kernel<<<SL_BLOCKS, 128>>>(ps, pt, pc, labels, scene, thr);       // #4
    combine_kernel<<<1, 1024>>>(out);                                            // #5
}